// round 4
// baseline (speedup 1.0000x reference)
#include <cuda_runtime.h>

#define NTAGS   1024
#define NCTA    128
#define TPB     256
#define ROWS    8            // tag rows per CTA (= warps per CTA)
#define TSTEPS  65536
#define SPIN_CAP (1u << 24)  // watchdog: unreachable in normal operation

// Persistent device state. Each entry packs {f32 alpha, u32 tag} in 8 bytes so
// a single relaxed b64 load atomically observes value+readiness together.
__device__ __align__(16) unsigned long long g_ab[2][NTAGS];
__device__ unsigned g_gen = 0;   // bumped once per launch by CTA0 (replay-safe tags)

__device__ __forceinline__ unsigned long long ld_rlx(const unsigned long long* p) {
    unsigned long long v;
    asm volatile("ld.relaxed.gpu.global.b64 %0, [%1];" : "=l"(v) : "l"(p));
    return v;
}
__device__ __forceinline__ void st_rlx(unsigned long long* p, unsigned long long v) {
    asm volatile("st.relaxed.gpu.global.b64 [%0], %1;" :: "l"(p), "l"(v) : "memory");
}
__device__ __forceinline__ unsigned long long pack_av(float a, unsigned tag) {
    return ((unsigned long long)tag << 32) | (unsigned long long)__float_as_uint(a);
}
__device__ __forceinline__ float val_of(unsigned long long q) {
    return __uint_as_float((unsigned)q);
}
__device__ __forceinline__ unsigned tag_of(unsigned long long q) {
    return (unsigned)(q >> 32);
}

__global__ void __launch_bounds__(TPB, 1)
crf_kernel(const float* __restrict__ unary,
           const float* __restrict__ trans,
           const int*   __restrict__ start_p,
           const int*   __restrict__ end_p,
           float*       __restrict__ out)
{
    const int tid  = threadIdx.x;
    const int lane = tid & 31;
    const int w    = tid >> 5;           // 8 warps
    const int cta  = blockIdx.x;
    const int base = cta * ROWS;
    const int row  = base + w;           // this warp's tag row

    __shared__ float sx[2][NTAGS];       // exp(alpha - m), double-buffered
    __shared__ float s_a[2][ROWS];       // this CTA's alpha rows, double-buffered
    __shared__ int   s_bail;             // watchdog flag

    const unsigned gen = g_gen;          // written by previous launch; stream-ordered
    // tag(step s) = gen*65536 + s + 1  (never 0, unique across replays)

    if (tid == 0) s_bail = 0;

    // ---- E row in registers: warp w owns row `row`, lane owns cols {lane+32k}
    float E[32];
    #pragma unroll
    for (int k = 0; k < 32; k++)
        E[k] = __expf(__ldg(&trans[(size_t)row * NTAGS + lane + 32 * k]));

    // ---- Step 0: alpha_0[i] = trans[i, start] + u_0[i]  (init alphas one-hot)
    float u_next = 0.0f;                 // lane0-only: unary for the next step
    if (lane == 0) {
        const int sidx = *start_p;
        const float a0 = __ldg(&trans[(size_t)row * NTAGS + sidx]) + __ldg(&unary[row]);
        s_a[0][w] = a0;
        s_a[1][w] = a0;                  // stands in for alpha_{-1} in m at t=1,2
        st_rlx(&g_ab[0][row], pack_av(a0, gen * 65536u + 1u));
        u_next = __ldcs(&unary[(size_t)NTAGS + row]);
    }
    __syncthreads();

    // ---- Main scan: ONE barrier per step --------------------------------
    for (int t = 1; t < TSTEPS; t++) {
        // exp-offset from alpha_{t-2} local rows (race-free: separated from the
        // producing writes by the previous iteration's __syncthreads).
        float mm = s_a[t & 1][0];
        #pragma unroll
        for (int r = 1; r < ROWS; r++) mm = fmaxf(mm, s_a[t & 1][r]);
        const float m = mm + 30.0f;

        // Poll alpha_{t-1} directly (tag == ready), all 4 quarters per round so
        // the L2 round trips overlap. Watchdog-bounded.
        const unsigned want = gen * 65536u + (unsigned)t;      // tag of step t-1
        const unsigned long long* src = g_ab[(t - 1) & 1];
        unsigned long long q0, q1, q2, q3;
        unsigned spins = 0;
        for (;;) {
            q0 = ld_rlx(src + tid);       q1 = ld_rlx(src + tid + 256);
            q2 = ld_rlx(src + tid + 512); q3 = ld_rlx(src + tid + 768);
            if (((tag_of(q0) ^ want) | (tag_of(q1) ^ want) |
                 (tag_of(q2) ^ want) | (tag_of(q3) ^ want)) == 0u) break;
            if (++spins > SPIN_CAP) { s_bail = 1; break; }
        }
        __syncthreads();                 // doubles as the bail broadcast point
        if (s_bail) break;               // hang -> fast wrong answer, not a dead GPU

        float* sxb = sx[t & 1];
        sxb[tid]       = __expf(val_of(q0) - m);
        sxb[tid + 256] = __expf(val_of(q1) - m);
        sxb[tid + 512] = __expf(val_of(q2) - m);
        sxb[tid + 768] = __expf(val_of(q3) - m);
        __syncthreads();

        // Row stage: warp w computes row `row` over all 1024 cols.
        const float* __restrict__ sxr = sx[t & 1];
        float a0 = 0.f, a1 = 0.f, a2 = 0.f, a3 = 0.f;
        #pragma unroll
        for (int k = 0; k < 32; k += 4) {
            a0 = fmaf(E[k + 0], sxr[lane + 32 * (k + 0)], a0);
            a1 = fmaf(E[k + 1], sxr[lane + 32 * (k + 1)], a1);
            a2 = fmaf(E[k + 2], sxr[lane + 32 * (k + 2)], a2);
            a3 = fmaf(E[k + 3], sxr[lane + 32 * (k + 3)], a3);
        }
        float S = (a0 + a1) + (a2 + a3);
        #pragma unroll
        for (int msk = 16; msk >= 1; msk >>= 1)
            S += __shfl_xor_sync(0xffffffffu, S, msk);

        if (lane == 0) {
            const float alpha = __logf(S) + m + u_next;
            s_a[t & 1][w] = alpha;
            st_rlx(&g_ab[t & 1][row], pack_av(alpha, want + 1u));
            const int tn = (t + 1 < TSTEPS) ? t + 1 : t;
            u_next = __ldcs(&unary[(size_t)tn * NTAGS + row]);
        }
        // no trailing barrier: next iteration's __syncthreads provides ordering
    }

    // ---- Terminal logsumexp (CTA 0) -------------------------------------
    if (cta == 0) {
        const unsigned want = gen * 65536u + (unsigned)TSTEPS; // tag of step T-1
        const unsigned long long* src = g_ab[(TSTEPS - 1) & 1];
        unsigned long long q0, q1, q2, q3;
        unsigned spins = 0;
        for (;;) {
            q0 = ld_rlx(src + tid);       q1 = ld_rlx(src + tid + 256);
            q2 = ld_rlx(src + tid + 512); q3 = ld_rlx(src + tid + 768);
            if (((tag_of(q0) ^ want) | (tag_of(q1) ^ want) |
                 (tag_of(q2) ^ want) | (tag_of(q3) ^ want)) == 0u) break;
            if (++spins > SPIN_CAP) break;
        }

        const int eidx = *end_p;
        const float x0 = val_of(q0) + __ldg(&trans[(size_t)eidx * NTAGS + tid]);
        const float x1 = val_of(q1) + __ldg(&trans[(size_t)eidx * NTAGS + tid + 256]);
        const float x2 = val_of(q2) + __ldg(&trans[(size_t)eidx * NTAGS + tid + 512]);
        const float x3 = val_of(q3) + __ldg(&trans[(size_t)eidx * NTAGS + tid + 768]);

        float mx = fmaxf(fmaxf(x0, x1), fmaxf(x2, x3));
        #pragma unroll
        for (int msk = 16; msk >= 1; msk >>= 1)
            mx = fmaxf(mx, __shfl_xor_sync(0xffffffffu, mx, msk));
        float* s_red = sx[0];
        if (lane == 0) s_red[w] = mx;
        __syncthreads();
        float M = s_red[0];
        #pragma unroll
        for (int w2 = 1; w2 < 8; w2++) M = fmaxf(M, s_red[w2]);

        float s = __expf(x0 - M) + __expf(x1 - M) + __expf(x2 - M) + __expf(x3 - M);
        #pragma unroll
        for (int msk = 16; msk >= 1; msk >>= 1)
            s += __shfl_xor_sync(0xffffffffu, s, msk);
        if (lane == 0) s_red[16 + w] = s;
        __syncthreads();

        if (tid == 0) {
            float Ssum = s_red[16];
            #pragma unroll
            for (int w2 = 1; w2 < 8; w2++) Ssum += s_red[16 + w2];
            out[0] = __logf(Ssum) + M;
            g_gen = gen + 1;             // version tags for the next replay
        }
    }
}

extern "C" void kernel_launch(void* const* d_in, const int* in_sizes, int n_in,
                              void* d_out, int out_size)
{
    const float* unary = (const float*)d_in[0];   // [65536, 1024] f32
    const float* trans = (const float*)d_in[1];   // [1024, 1024]  f32
    const int*   sidx  = (const int*)d_in[2];     // scalar
    const int*   eidx  = (const int*)d_in[3];     // scalar
    float*       out   = (float*)d_out;           // scalar f32

    crf_kernel<<<NCTA, TPB>>>(unary, trans, sidx, eidx, out);
}

// round 5
// speedup vs baseline: 1.3831x; 1.3831x over previous
#include <cuda_runtime.h>

#define NTAGS   1024
#define NCTA    128
#define TPB     256
#define ROWS    8            // tag rows per CTA (= warps per CTA)
#define TSTEPS  65536
#define SPIN_CAP (1u << 24)  // watchdog: unreachable in normal operation

// Persistent device state.
// g_ab: each entry packs {f32 alpha, u32 tag} so one b64 load observes
//       value+readiness atomically (no fences needed anywhere).
// g_rep: one tag per producer CTA, contiguous (4 cache lines) -> cheap polling.
__device__ __align__(16) unsigned long long g_ab[2][NTAGS];
__device__ __align__(16) unsigned           g_rep[2][NCTA];
__device__ unsigned g_gen = 0;   // bumped once per launch (replay-safe tags)

__device__ __forceinline__ unsigned long long ld_rlx64(const unsigned long long* p) {
    unsigned long long v;
    asm volatile("ld.relaxed.gpu.global.b64 %0, [%1];" : "=l"(v) : "l"(p));
    return v;
}
__device__ __forceinline__ void st_rlx64(unsigned long long* p, unsigned long long v) {
    asm volatile("st.relaxed.gpu.global.b64 [%0], %1;" :: "l"(p), "l"(v) : "memory");
}
__device__ __forceinline__ unsigned ld_rlx32(const unsigned* p) {
    unsigned v;
    asm volatile("ld.relaxed.gpu.global.u32 %0, [%1];" : "=r"(v) : "l"(p));
    return v;
}
__device__ __forceinline__ void st_rlx32(unsigned* p, unsigned v) {
    asm volatile("st.relaxed.gpu.global.u32 [%0], %1;" :: "l"(p), "r"(v) : "memory");
}
__device__ __forceinline__ unsigned long long pack_av(float a, unsigned tag) {
    return ((unsigned long long)tag << 32) | (unsigned long long)__float_as_uint(a);
}
__device__ __forceinline__ float    val_of(unsigned long long q) { return __uint_as_float((unsigned)q); }
__device__ __forceinline__ unsigned tag_of(unsigned long long q) { return (unsigned)(q >> 32); }

__global__ void __launch_bounds__(TPB, 1)
crf_kernel(const float* __restrict__ unary,
           const float* __restrict__ trans,
           const int*   __restrict__ start_p,
           const int*   __restrict__ end_p,
           float*       __restrict__ out)
{
    const int tid  = threadIdx.x;
    const int lane = tid & 31;
    const int w    = tid >> 5;           // 8 warps
    const int cta  = blockIdx.x;
    const int row  = cta * ROWS + w;     // this warp's tag row

    __shared__ float sx[NTAGS];          // exp(alpha - m); single buffer (see proof below)
    __shared__ float s_a[2][ROWS];       // this CTA's alpha rows, double-buffered
    __shared__ int   s_bail;             // watchdog flag

    const unsigned gen = g_gen;          // stream-ordered across graph replays
    // tag(step s) = gen*65536 + s + 1  (never 0, unique across replays)

    if (tid == 0) s_bail = 0;

    // ---- E row in registers: warp w owns row `row`, lane owns cols {lane+32k}
    float E[32];
    #pragma unroll
    for (int k = 0; k < 32; k++)
        E[k] = __expf(__ldg(&trans[(size_t)row * NTAGS + lane + 32 * k]));

    // ---- Step 0: alpha_0[i] = trans[i, start] + u_0[i] ------------------
    float u_next = 0.0f;                 // lane0-only: unary for the next step
    if (lane == 0) {
        const int sidx = *start_p;
        const float a0 = __ldg(&trans[(size_t)row * NTAGS + sidx]) + __ldg(&unary[row]);
        s_a[0][w] = a0;
        s_a[1][w] = a0;                  // stands in for alpha_{-1} at t=1,2
        st_rlx64(&g_ab[0][row], pack_av(a0, gen * 65536u + 1u));
        if (w == ROWS - 1) st_rlx32(&g_rep[0][cta], gen * 65536u + 1u);
        u_next = __ldcs(&unary[(size_t)NTAGS + row]);
    }
    __syncthreads();

    // ---- Main scan ------------------------------------------------------
    for (int t = 1; t < TSTEPS; t++) {
        const int pb = (t - 1) & 1;      // buffer holding alpha_{t-1}
        const int b  = t & 1;

        // exp-offset from alpha_{t-2} (race-free via double buffer + barriers).
        float mm = s_a[b][0];
        #pragma unroll
        for (int r = 1; r < ROWS; r++) mm = fmaxf(mm, s_a[b][r]);
        const float m = mm + 30.0f;      // covers 2 steps of drift (< 26)

        const unsigned want = gen * 65536u + (unsigned)t;  // tag of step t-1

        // NARROW poll: warp 0 spins on the 128 contiguous rep tags (4 lines).
        if (w == 0) {
            unsigned spins = 0;
            for (;;) {
                const unsigned r0 = ld_rlx32(&g_rep[pb][lane]);
                const unsigned r1 = ld_rlx32(&g_rep[pb][lane + 32]);
                const unsigned r2 = ld_rlx32(&g_rep[pb][lane + 64]);
                const unsigned r3 = ld_rlx32(&g_rep[pb][lane + 96]);
                const bool ok = ((r0 ^ want) | (r1 ^ want) |
                                 (r2 ^ want) | (r3 ^ want)) == 0u;
                if (__all_sync(0xffffffffu, ok)) break;
                if (++spins > SPIN_CAP) { s_bail = 1; break; }
            }
        }
        __syncthreads();                 // release consumers; bail broadcast point
        if (s_bail) break;

        // WIDE load exactly once, self-verifying (retries are rare stragglers).
        const unsigned long long* src = g_ab[pb];
        unsigned long long q0 = ld_rlx64(src + tid);
        unsigned long long q1 = ld_rlx64(src + tid + 256);
        unsigned long long q2 = ld_rlx64(src + tid + 512);
        unsigned long long q3 = ld_rlx64(src + tid + 768);
        {
            unsigned spins = 0;
            while (((tag_of(q0) ^ want) | (tag_of(q1) ^ want) |
                    (tag_of(q2) ^ want) | (tag_of(q3) ^ want)) != 0u) {
                q0 = ld_rlx64(src + tid);       q1 = ld_rlx64(src + tid + 256);
                q2 = ld_rlx64(src + tid + 512); q3 = ld_rlx64(src + tid + 768);
                if (++spins > SPIN_CAP) break;
            }
        }

        // sx single-buffer safety: reads of sx at step t happen before this
        // warp reaches the next iteration's first __syncthreads; writes at
        // t+1 happen after it. No overlap.
        sx[tid]       = __expf(val_of(q0) - m);
        sx[tid + 256] = __expf(val_of(q1) - m);
        sx[tid + 512] = __expf(val_of(q2) - m);
        sx[tid + 768] = __expf(val_of(q3) - m);
        __syncthreads();

        // Row stage: warp w computes row `row` over all 1024 cols.
        float a0 = 0.f, a1 = 0.f, a2 = 0.f, a3 = 0.f;
        #pragma unroll
        for (int k = 0; k < 32; k += 4) {
            a0 = fmaf(E[k + 0], sx[lane + 32 * (k + 0)], a0);
            a1 = fmaf(E[k + 1], sx[lane + 32 * (k + 1)], a1);
            a2 = fmaf(E[k + 2], sx[lane + 32 * (k + 2)], a2);
            a3 = fmaf(E[k + 3], sx[lane + 32 * (k + 3)], a3);
        }
        float S = (a0 + a1) + (a2 + a3);
        #pragma unroll
        for (int msk = 16; msk >= 1; msk >>= 1)
            S += __shfl_xor_sync(0xffffffffu, S, msk);

        if (lane == 0) {
            const float alpha = __logf(S) + m + u_next;
            s_a[b][w] = alpha;
            st_rlx64(&g_ab[b][row], pack_av(alpha, want + 1u));
            if (w == ROWS - 1) st_rlx32(&g_rep[b][cta], want + 1u);
            const int tn = (t + 1 < TSTEPS) ? t + 1 : t;
            u_next = __ldcs(&unary[(size_t)tn * NTAGS + row]);
        }
        // no trailing barrier: next iteration's barriers provide ordering
    }

    // ---- Terminal logsumexp (CTA 0) -------------------------------------
    if (cta == 0) {
        const unsigned want = gen * 65536u + (unsigned)TSTEPS; // tag of step T-1
        const unsigned long long* src = g_ab[(TSTEPS - 1) & 1];
        unsigned long long q0 = ld_rlx64(src + tid);
        unsigned long long q1 = ld_rlx64(src + tid + 256);
        unsigned long long q2 = ld_rlx64(src + tid + 512);
        unsigned long long q3 = ld_rlx64(src + tid + 768);
        {
            unsigned spins = 0;
            while (((tag_of(q0) ^ want) | (tag_of(q1) ^ want) |
                    (tag_of(q2) ^ want) | (tag_of(q3) ^ want)) != 0u) {
                q0 = ld_rlx64(src + tid);       q1 = ld_rlx64(src + tid + 256);
                q2 = ld_rlx64(src + tid + 512); q3 = ld_rlx64(src + tid + 768);
                if (++spins > SPIN_CAP) break;
            }
        }

        const int eidx = *end_p;
        const float x0 = val_of(q0) + __ldg(&trans[(size_t)eidx * NTAGS + tid]);
        const float x1 = val_of(q1) + __ldg(&trans[(size_t)eidx * NTAGS + tid + 256]);
        const float x2 = val_of(q2) + __ldg(&trans[(size_t)eidx * NTAGS + tid + 512]);
        const float x3 = val_of(q3) + __ldg(&trans[(size_t)eidx * NTAGS + tid + 768]);

        float mx = fmaxf(fmaxf(x0, x1), fmaxf(x2, x3));
        #pragma unroll
        for (int msk = 16; msk >= 1; msk >>= 1)
            mx = fmaxf(mx, __shfl_xor_sync(0xffffffffu, mx, msk));
        if (lane == 0) sx[w] = mx;
        __syncthreads();
        float M = sx[0];
        #pragma unroll
        for (int w2 = 1; w2 < 8; w2++) M = fmaxf(M, sx[w2]);

        float s = __expf(x0 - M) + __expf(x1 - M) + __expf(x2 - M) + __expf(x3 - M);
        #pragma unroll
        for (int msk = 16; msk >= 1; msk >>= 1)
            s += __shfl_xor_sync(0xffffffffu, s, msk);
        if (lane == 0) sx[16 + w] = s;
        __syncthreads();

        if (tid == 0) {
            float Ssum = sx[16];
            #pragma unroll
            for (int w2 = 1; w2 < 8; w2++) Ssum += sx[16 + w2];
            out[0] = __logf(Ssum) + M;
            g_gen = gen + 1;             // version tags for the next replay
        }
    }
}

extern "C" void kernel_launch(void* const* d_in, const int* in_sizes, int n_in,
                              void* d_out, int out_size)
{
    const float* unary = (const float*)d_in[0];   // [65536, 1024] f32
    const float* trans = (const float*)d_in[1];   // [1024, 1024]  f32
    const int*   sidx  = (const int*)d_in[2];     // scalar
    const int*   eidx  = (const int*)d_in[3];     // scalar
    float*       out   = (float*)d_out;           // scalar f32

    crf_kernel<<<NCTA, TPB>>>(unary, trans, sidx, eidx, out);
}